// round 6
// baseline (speedup 1.0000x reference)
#include <cuda_runtime.h>
#include <cstddef>

// MultiLayerLSTM: T=1024, B=64, C=256, H=512, fp32.
// Decoupled wavefront: 64 CTAs run layer0 at their own pace (internal barrier
// only), 64 CTAs run layer1 (internal barrier for its h, cross-barrier on
// layer0's progress for its x-part = g_y0). Layer1 orders h-part first so
// layer0's tail is hidden. 256 thr/CTA, 8 hidden/CTA, 8m x 8n x 8kg tile,
// f32x2 FMA, KC=128 chunks, shuffle k-reduction (no SMEM partials).

#define T_    1024
#define B_    64
#define C_    256
#define H_    512
#define GRID_ 128
#define NTHR_ 256
#define KC_   128

// ---- shared memory layout (float offsets) ----
#define OFF_W   0
#define SZ_W    (32 * 1028)           // 32 gate rows x K(<=1024), pad 1028
#define OFF_A0  (OFF_W + SZ_W)
#define ABUF_F  8320                  // 64 k-pairs x 65 f32x2
#define OFF_A1  (OFF_A0 + ABUF_F)
#define OFF_G   (OFF_A1 + ABUF_F)
#define SZ_G    (32 * 68)
#define OFF_C   (OFF_G + SZ_G)
#define SZ_C    (8 * 65)
#define OFF_H   (OFF_C + SZ_C)
#define SZ_H    512
#define OFF_B   (OFF_H + SZ_H)
#define SMEM_FLOATS (OFF_B + 32)
#define SMEM_BYTES  (SMEM_FLOATS * 4)   // ~211 KB -> 1 CTA/SM

static __device__ float g_y0[(size_t)T_ * B_ * H_];   // layer-0 outputs
static __device__ int   g_bars0[8 * 32];              // layer-0 arrivals (8 ctrs)
static __device__ int   g_bars1[8 * 32];              // layer-1 arrivals

__global__ void reset_kernel() {
    if (threadIdx.x < 8) {
        g_bars0[threadIdx.x * 32] = 0;
        g_bars1[threadIdx.x * 32] = 0;
    }
}

__device__ __forceinline__ void fma2(unsigned long long& d, unsigned long long a,
                                     unsigned long long b) {
    asm("fma.rn.f32x2 %0, %1, %2, %0;" : "+l"(d) : "l"(a), "l"(b));
}
__device__ __forceinline__ float sigf(float v) { return 1.0f / (1.0f + __expf(-v)); }

extern __shared__ float sm[];

__device__ __forceinline__ void wait_bars(const int* bars, int tid, int target) {
    if (tid < 8) {
        volatile const int* p = bars + tid * 32;
        while (*p < target) { }
        __threadfence();
    }
    __syncthreads();
}

// load one 128-k chunk (8 float4/thread) from global
__device__ __forceinline__ void ldg8(const float* __restrict__ src, int rs, int col,
                                     int tid, float4* v) {
    #pragma unroll
    for (int it = 0; it < 8; it++) {
        const int f = it * NTHR_ + tid;
        const int k4 = f & 31, m = f >> 5;
        v[it] = *(const float4*)(src + (size_t)m * rs + col + k4 * 4);
    }
}
// store it transposed (k-pair-major) into an A buffer
__device__ __forceinline__ void sts8(float* buf, int tid, const float4* v) {
    float2* b2 = (float2*)buf;
    #pragma unroll
    for (int it = 0; it < 8; it++) {
        const int f = it * NTHR_ + tid;
        const int k4 = f & 31, m = f >> 5;
        b2[(2 * k4) * 65 + m]     = make_float2(v[it].x, v[it].y);
        b2[(2 * k4 + 1) * 65 + m] = make_float2(v[it].z, v[it].w);
    }
}

// compute one chunk: 64 k-pairs, 8 per kg thread
__device__ __forceinline__ void compute_chunk(const float* buf, int wbase,
                                              int kg, int mg, int ng,
                                              unsigned long long* acc) {
    const unsigned long long* Ab = (const unsigned long long*)buf;
    const unsigned long long* Wp = (const unsigned long long*)(sm + OFF_W); // stride 514
    #pragma unroll
    for (int i = 0; i < 8; i++) {
        const int kp = i * 8 + kg;
        const unsigned long long* Ar = Ab + kp * 65 + mg * 8;
        unsigned long long a[8];
        #pragma unroll
        for (int mm = 0; mm < 8; mm++) a[mm] = Ar[mm];
        const unsigned long long* Wr = Wp + (ng * 8) * 514 + wbase + kp;
        unsigned long long w[8];
        #pragma unroll
        for (int nn = 0; nn < 8; nn++) w[nn] = Wr[nn * 514];
        #pragma unroll
        for (int nn = 0; nn < 8; nn++)
            #pragma unroll
            for (int mm = 0; mm < 8; mm++)
                fma2(acc[mm * 8 + nn], a[mm], w[nn]);
    }
}

// one LSTM timestep: segment A chunks [ca0,ca1) from srcA, then segment B
// chunks [cb0,cb1) from srcB; optional barrier wait before each segment.
__device__ __forceinline__ void lstm_step(
    int tid, int j0,
    const float* srcA, int rsA, int ca0, int ca1, const int* barsA, int targA,
    const float* srcB, int rsB, int cb0, int cb1, const int* barsB, int targB,
    float* __restrict__ hrow, bool last,
    float* __restrict__ hTd, float* __restrict__ cTd, int* arrive_ctr)
{
    float* AbufA = sm + OFF_A0;
    float* AbufB = sm + OFF_A1;
    float* Gr    = sm + OFF_G;
    float* Cs    = sm + OFF_C;
    float* Hs    = sm + OFF_H;
    float* Bs    = sm + OFF_B;

    const int kg = tid & 7;
    const int mg = (tid >> 3) & 7;
    const int ng = tid >> 6;

    unsigned long long acc[64];
    #pragma unroll
    for (int i = 0; i < 64; i++) acc[i] = 0ull;

    int ci = 0;
    #pragma unroll
    for (int sg = 0; sg < 2; sg++) {
        const float* src = sg ? srcB : srcA;
        const int rs  = sg ? rsB : rsA;
        const int c0  = sg ? cb0 : ca0;
        const int c1  = sg ? cb1 : ca1;
        const int* bw = sg ? barsB : barsA;
        const int tw  = sg ? targB : targA;

        if (bw) wait_bars(bw, tid, tw);

        {   // direct-stage first chunk of segment
            float4 v[8];
            ldg8(src, rs, 0, tid, v);
            sts8((ci & 1) ? AbufB : AbufA, tid, v);
        }
        for (int c = c0; c < c1; c++) {
            __syncthreads();            // staged buffer visible; other buffer free
            float4 v[8];
            const bool pf = (c + 1 < c1);
            if (pf) ldg8(src, rs, (c + 1 - c0) * KC_, tid, v);
            compute_chunk((ci & 1) ? AbufB : AbufA, c * 64, kg, mg, ng, acc);
            if (pf) sts8((ci & 1) ? AbufA : AbufB, tid, v);
            ci++;
        }
    }

    // ---- fold f32x2 lanes ----
    float s0[64];
    #pragma unroll
    for (int i = 0; i < 64; i++) {
        const unsigned long long a = acc[i];
        s0[i] = __uint_as_float((unsigned)(a & 0xffffffffull)) +
                __uint_as_float((unsigned)(a >> 32));
    }
    // ---- shuffle k-reduction across kg (lanes 0-2), result owner nn == kg ----
    #pragma unroll
    for (int i = 0; i < 64; i++) s0[i] += __shfl_xor_sync(0xffffffffu, s0[i], 1);
    float s1[32];
    {
        const bool p = (kg & 1);
        #pragma unroll
        for (int mm = 0; mm < 8; mm++)
            #pragma unroll
            for (int q = 0; q < 4; q++)
                s1[mm * 4 + q] = p ? s0[mm * 8 + 2 * q + 1] : s0[mm * 8 + 2 * q];
    }
    #pragma unroll
    for (int i = 0; i < 32; i++) s1[i] += __shfl_xor_sync(0xffffffffu, s1[i], 2);
    float s2[16];
    {
        const bool p = (kg & 2);
        #pragma unroll
        for (int mm = 0; mm < 8; mm++)
            #pragma unroll
            for (int q = 0; q < 2; q++)
                s2[mm * 2 + q] = p ? s1[mm * 4 + 2 * q + 1] : s1[mm * 4 + 2 * q];
    }
    #pragma unroll
    for (int i = 0; i < 16; i++) s2[i] += __shfl_xor_sync(0xffffffffu, s2[i], 4);
    float s3[8];
    {
        const bool p = (kg & 4);
        #pragma unroll
        for (int mm = 0; mm < 8; mm++)
            s3[mm] = p ? s2[mm * 2 + 1] : s2[mm * 2];
    }
    // thread now holds gate pre-activations for n = ng*8+kg, m = mg*8 + 0..7
    {
        const int n = ng * 8 + kg;
        const float bn = Bs[n];
        float* g = &Gr[n * 68 + mg * 8];
        *(float4*)(g)     = make_float4(s3[0] + bn, s3[1] + bn, s3[2] + bn, s3[3] + bn);
        *(float4*)(g + 4) = make_float4(s3[4] + bn, s3[5] + bn, s3[6] + bn, s3[7] + bn);
    }
    __syncthreads();

    // ---- pointwise: 512 cells, 2 per thread ----
    {
        const int m = tid & 63;
        const int jb = tid >> 6;
        #pragma unroll
        for (int u = 0; u < 2; u++) {
            const int jj = jb + u * 4;
            const float gi = sigf(Gr[jj * 68 + m]);
            const float gf = sigf(Gr[(8 + jj) * 68 + m]);
            const float gc = tanhf(Gr[(16 + jj) * 68 + m]);
            const float go = sigf(Gr[(24 + jj) * 68 + m]);
            const float cv = gf * Cs[jj * 65 + m] + gi * gc;
            Cs[jj * 65 + m] = cv;
            Hs[m * 8 + jj] = go * tanhf(cv);
            if (last) cTd[(size_t)m * H_ + j0 + jj] = cv;
        }
    }
    __syncthreads();

    // ---- write h slice (64 m x 8 j), then arrive on this layer's barrier ----
    if (tid < 128) {
        const int m = tid >> 1, q = tid & 1;
        const float4 hv = *(const float4*)&Hs[m * 8 + q * 4];
        *(float4*)(hrow + (size_t)m * H_ + j0 + q * 4) = hv;
        if (last) *(float4*)(hTd + (size_t)m * H_ + j0 + q * 4) = hv;
        __threadfence();
    }
    __syncthreads();
    if (tid == 0) atomicAdd(arrive_ctr, 1);
}

__global__ void __launch_bounds__(NTHR_, 1) lstm_kernel(
    const float* __restrict__ x,
    const float* __restrict__ h00, const float* __restrict__ c00,
    const float* __restrict__ h01, const float* __restrict__ c01,
    const float* __restrict__ Wih0, const float* __restrict__ Whh0,
    const float* __restrict__ bih0, const float* __restrict__ bhh0,
    const float* __restrict__ Wih1, const float* __restrict__ Whh1,
    const float* __restrict__ bih1, const float* __restrict__ bhh1,
    float* out)
{
    const int tid  = threadIdx.x;
    const int bid  = blockIdx.x;
    const int role = bid >> 6;            // 0: layer0, 1: layer1
    const int j0   = (bid & 63) * 8;
    const int grp  = (bid & 63) >> 3;     // 8 counters x 8 CTAs per layer

    float* Wsf = sm + OFF_W;
    float* Cs  = sm + OFF_C;
    float* Bs  = sm + OFF_B;

    float* yout = out;
    float* h1f  = out + (size_t)T_ * B_ * H_;
    float* c1f  = h1f + B_ * H_;
    float* h2f  = c1f + B_ * H_;
    float* c2f  = h2f + B_ * H_;

    const int KX = (role == 0) ? C_ : H_;
    const int K  = KX + H_;
    const float* Wx    = (role == 0) ? Wih0 : Wih1;
    const float* Wh    = (role == 0) ? Whh0 : Whh1;
    const float* bi    = (role == 0) ? bih0 : bih1;
    const float* bh    = (role == 0) ? bhh0 : bhh1;
    const float* cinit = (role == 0) ? c00 : c01;

    // ---- one-time setup: weights [32 rows][K] = [Wx | Wh], bias, cell ----
    for (int idx = tid; idx < 32 * K; idx += NTHR_) {
        const int n = idx / K, k = idx - n * K;
        const int gr = (n >> 3) * H_ + j0 + (n & 7);
        const float v = (k < KX) ? Wx[(size_t)gr * KX + k]
                                 : Wh[(size_t)gr * H_ + (k - KX)];
        Wsf[n * 1028 + k] = v;
    }
    if (tid < 32) {
        const int gr = (tid >> 3) * H_ + j0 + (tid & 7);
        Bs[tid] = bi[gr] + bh[gr];
    }
    {
        const int m = tid & 63, jb = tid >> 6;
        Cs[jb * 65 + m]       = cinit[(size_t)m * H_ + j0 + jb];
        Cs[(jb + 4) * 65 + m] = cinit[(size_t)m * H_ + j0 + jb + 4];
    }
    __syncthreads();

    if (role == 0) {
        // layer0: x chunks [0,2) free, then h chunks [2,6) after own barrier
        for (int t = 0; t < T_; t++) {
            const float* hprev = (t == 0) ? h00 : (g_y0 + (size_t)(t - 1) * B_ * H_);
            lstm_step(tid, j0,
                      x + (size_t)t * B_ * C_, C_, 0, 2, nullptr, 0,
                      hprev, H_, 2, 6, g_bars0, t * 8,
                      g_y0 + (size_t)t * B_ * H_, t == T_ - 1, h1f, c1f,
                      &g_bars0[grp * 32]);
        }
    } else {
        // layer1: h chunks [4,8) after own barrier, then x chunks [0,4)
        // (src g_y0[t]) after layer0's barrier reaches t+1.
        for (int t = 0; t < T_; t++) {
            const float* hprev = (t == 0) ? h01 : (yout + (size_t)(t - 1) * B_ * H_);
            lstm_step(tid, j0,
                      hprev, H_, 4, 8, g_bars1, t * 8,
                      g_y0 + (size_t)t * B_ * H_, H_, 0, 4, g_bars0, (t + 1) * 8,
                      yout + (size_t)t * B_ * H_, t == T_ - 1, h2f, c2f,
                      &g_bars1[grp * 32]);
        }
    }
}

extern "C" void kernel_launch(void* const* d_in, const int* in_sizes, int n_in,
                              void* d_out, int out_size) {
    (void)in_sizes; (void)n_in; (void)out_size;
    cudaFuncSetAttribute(lstm_kernel, cudaFuncAttributeMaxDynamicSharedMemorySize,
                         SMEM_BYTES);
    reset_kernel<<<1, 32>>>();
    lstm_kernel<<<GRID_, NTHR_, SMEM_BYTES>>>(
        (const float*)d_in[0],
        (const float*)d_in[1], (const float*)d_in[2],
        (const float*)d_in[3], (const float*)d_in[4],
        (const float*)d_in[5], (const float*)d_in[6],
        (const float*)d_in[7], (const float*)d_in[8],
        (const float*)d_in[9], (const float*)d_in[10],
        (const float*)d_in[11], (const float*)d_in[12],
        (float*)d_out);
}

// round 7
// speedup vs baseline: 1.0608x; 1.0608x over previous
#include <cuda_runtime.h>
#include <cstddef>

// MultiLayerLSTM: T=1024, B=64, C=256, H=512, fp32.
// Decoupled wavefront: 64 CTAs run layer0 on its own barrier; 64 CTAs run
// layer1 (own barrier for h, cross-barrier on layer0 progress for x = g_y0,
// ordered h-part first). 256 thr/CTA, 8 hidden/CTA, 8m x 8n x 8kg tile,
// f32x2 FMA, KC=64 chunks (low reg pressure), mm-major shuffle k-reduction
// (no SMEM partials buffer).

#define T_    1024
#define B_    64
#define C_    256
#define H_    512
#define GRID_ 128
#define NTHR_ 256
#define KC_   64          // k per staged chunk
#define KP_   32          // k-pairs per chunk

// ---- shared memory layout (float offsets) ----
#define OFF_W   0
#define SZ_W    (32 * 1028)           // 32 gate rows x K(<=1024), pad 1028
#define OFF_A0  (OFF_W + SZ_W)
#define ABUF_F  (KP_ * 65 * 2)        // 32 k-pairs x 65 f32x2
#define OFF_A1  (OFF_A0 + ABUF_F)
#define OFF_G   (OFF_A1 + ABUF_F)
#define SZ_G    (32 * 68)
#define OFF_C   (OFF_G + SZ_G)
#define SZ_C    (8 * 65)
#define OFF_H   (OFF_C + SZ_C)
#define SZ_H    512
#define OFF_B   (OFF_H + SZ_H)
#define SMEM_FLOATS (OFF_B + 32)
#define SMEM_BYTES  (SMEM_FLOATS * 4)   // ~179 KB -> 1 CTA/SM

static __device__ float g_y0[(size_t)T_ * B_ * H_];   // layer-0 outputs
static __device__ int   g_bars0[8 * 32];              // layer-0 arrivals
static __device__ int   g_bars1[8 * 32];              // layer-1 arrivals

__global__ void reset_kernel() {
    if (threadIdx.x < 8) {
        g_bars0[threadIdx.x * 32] = 0;
        g_bars1[threadIdx.x * 32] = 0;
    }
}

__device__ __forceinline__ void fma2(unsigned long long& d, unsigned long long a,
                                     unsigned long long b) {
    asm("fma.rn.f32x2 %0, %1, %2, %0;" : "+l"(d) : "l"(a), "l"(b));
}
__device__ __forceinline__ float sigf(float v) { return 1.0f / (1.0f + __expf(-v)); }

extern __shared__ float sm[];

__device__ __forceinline__ void wait_bars(const int* bars, int tid, int target) {
    if (tid < 8) {
        volatile const int* p = bars + tid * 32;
        while (*p < target) { }
        __threadfence();
    }
    __syncthreads();
}

// load one 64-k chunk (4 float4/thread) from global
__device__ __forceinline__ void ldg4(const float* __restrict__ src, int rs, int col,
                                     int tid, float4* v) {
    #pragma unroll
    for (int it = 0; it < 4; it++) {
        const int f = it * NTHR_ + tid;
        const int k4 = f & 15, m = f >> 4;
        v[it] = *(const float4*)(src + (size_t)m * rs + col + k4 * 4);
    }
}
// store it transposed (k-pair-major) into an A buffer
__device__ __forceinline__ void sts4(float* buf, int tid, const float4* v) {
    float2* b2 = (float2*)buf;
    #pragma unroll
    for (int it = 0; it < 4; it++) {
        const int f = it * NTHR_ + tid;
        const int k4 = f & 15, m = f >> 4;
        b2[(2 * k4) * 65 + m]     = make_float2(v[it].x, v[it].y);
        b2[(2 * k4 + 1) * 65 + m] = make_float2(v[it].z, v[it].w);
    }
}

// compute one chunk: 32 k-pairs, 4 per kg thread
__device__ __forceinline__ void compute_chunk(const float* buf, int wbase,
                                              int kg, int mg, int ng,
                                              unsigned long long* acc) {
    const unsigned long long* Ab = (const unsigned long long*)buf;
    const unsigned long long* Wp = (const unsigned long long*)(sm + OFF_W); // stride 514
    #pragma unroll
    for (int i = 0; i < 4; i++) {
        const int kp = i * 8 + kg;
        const unsigned long long* Ar = Ab + kp * 65 + mg * 8;
        unsigned long long a[8];
        #pragma unroll
        for (int mm = 0; mm < 8; mm++) a[mm] = Ar[mm];
        const unsigned long long* Wr = Wp + (ng * 8) * 514 + wbase + kp;
        unsigned long long w[8];
        #pragma unroll
        for (int nn = 0; nn < 8; nn++) w[nn] = Wr[nn * 514];
        #pragma unroll
        for (int nn = 0; nn < 8; nn++)
            #pragma unroll
            for (int mm = 0; mm < 8; mm++)
                fma2(acc[mm * 8 + nn], a[mm], w[nn]);
    }
}

// one LSTM timestep: segment A chunks [ca0,ca1) from srcA, then segment B
// chunks [cb0,cb1) from srcB; optional barrier wait before each segment.
__device__ __forceinline__ void lstm_step(
    int tid, int j0,
    const float* srcA, int rsA, int ca0, int ca1, const int* barsA, int targA,
    const float* srcB, int rsB, int cb0, int cb1, const int* barsB, int targB,
    float* __restrict__ hrow, bool last,
    float* __restrict__ hTd, float* __restrict__ cTd, int* arrive_ctr)
{
    float* AbufA = sm + OFF_A0;
    float* AbufB = sm + OFF_A1;
    float* Gr    = sm + OFF_G;
    float* Cs    = sm + OFF_C;
    float* Hs    = sm + OFF_H;
    float* Bs    = sm + OFF_B;

    const int kg = tid & 7;
    const int mg = (tid >> 3) & 7;
    const int ng = tid >> 6;

    unsigned long long acc[64];
    #pragma unroll
    for (int i = 0; i < 64; i++) acc[i] = 0ull;

    int ci = 0;
    #pragma unroll
    for (int sg = 0; sg < 2; sg++) {
        const float* src = sg ? srcB : srcA;
        const int rs  = sg ? rsB : rsA;
        const int c0  = sg ? cb0 : ca0;
        const int c1  = sg ? cb1 : ca1;
        const int* bw = sg ? barsB : barsA;
        const int tw  = sg ? targB : targA;

        if (bw) wait_bars(bw, tid, tw);

        {   // direct-stage first chunk of segment
            float4 v[4];
            ldg4(src, rs, 0, tid, v);
            sts4((ci & 1) ? AbufB : AbufA, tid, v);
        }
        for (int c = c0; c < c1; c++) {
            __syncthreads();            // staged buffer visible; other free
            float4 v[4];
            const bool pf = (c + 1 < c1);
            if (pf) ldg4(src, rs, (c + 1 - c0) * KC_, tid, v);
            compute_chunk((ci & 1) ? AbufB : AbufA, c * KP_, kg, mg, ng, acc);
            if (pf) sts4((ci & 1) ? AbufA : AbufB, tid, v);
            ci++;
        }
    }

    // ---- mm-major fold + shuffle k-reduction (<=8 live temps per mm) ----
    // kg lives in lane bits 0-2; after 3 xor rounds thread owns gate
    // n = ng*8 + kg for m = mg*8 + mm.
    float s3[8];
    #pragma unroll
    for (int mm = 0; mm < 8; mm++) {
        float r[8];
        #pragma unroll
        for (int nn = 0; nn < 8; nn++) {
            const unsigned long long a = acc[mm * 8 + nn];
            r[nn] = __uint_as_float((unsigned)(a & 0xffffffffull)) +
                    __uint_as_float((unsigned)(a >> 32));
        }
        #pragma unroll
        for (int nn = 0; nn < 8; nn++)
            r[nn] += __shfl_xor_sync(0xffffffffu, r[nn], 1);
        float t4[4];
        {
            const bool p = (kg & 1);
            #pragma unroll
            for (int q = 0; q < 4; q++) t4[q] = p ? r[2 * q + 1] : r[2 * q];
        }
        #pragma unroll
        for (int q = 0; q < 4; q++)
            t4[q] += __shfl_xor_sync(0xffffffffu, t4[q], 2);
        float t2[2];
        {
            const bool p = (kg & 2);
            #pragma unroll
            for (int q = 0; q < 2; q++) t2[q] = p ? t4[2 * q + 1] : t4[2 * q];
        }
        #pragma unroll
        for (int q = 0; q < 2; q++)
            t2[q] += __shfl_xor_sync(0xffffffffu, t2[q], 4);
        s3[mm] = (kg & 4) ? t2[1] : t2[0];
    }
    {
        const int n = ng * 8 + kg;
        const float bn = Bs[n];
        float* g = &Gr[n * 68 + mg * 8];
        *(float4*)(g)     = make_float4(s3[0] + bn, s3[1] + bn, s3[2] + bn, s3[3] + bn);
        *(float4*)(g + 4) = make_float4(s3[4] + bn, s3[5] + bn, s3[6] + bn, s3[7] + bn);
    }
    __syncthreads();

    // ---- pointwise: 512 cells, 2 per thread ----
    {
        const int m = tid & 63;
        const int jb = tid >> 6;
        #pragma unroll
        for (int u = 0; u < 2; u++) {
            const int jj = jb + u * 4;
            const float gi = sigf(Gr[jj * 68 + m]);
            const float gf = sigf(Gr[(8 + jj) * 68 + m]);
            const float gc = tanhf(Gr[(16 + jj) * 68 + m]);
            const float go = sigf(Gr[(24 + jj) * 68 + m]);
            const float cv = gf * Cs[jj * 65 + m] + gi * gc;
            Cs[jj * 65 + m] = cv;
            Hs[m * 8 + jj] = go * tanhf(cv);
            if (last) cTd[(size_t)m * H_ + j0 + jj] = cv;
        }
    }
    __syncthreads();

    // ---- write h slice (64 m x 8 j), then arrive on this layer's barrier ----
    if (tid < 128) {
        const int m = tid >> 1, q = tid & 1;
        const float4 hv = *(const float4*)&Hs[m * 8 + q * 4];
        *(float4*)(hrow + (size_t)m * H_ + j0 + q * 4) = hv;
        if (last) *(float4*)(hTd + (size_t)m * H_ + j0 + q * 4) = hv;
        __threadfence();
    }
    __syncthreads();
    if (tid == 0) atomicAdd(arrive_ctr, 1);
}

__global__ void __launch_bounds__(NTHR_, 1) lstm_kernel(
    const float* __restrict__ x,
    const float* __restrict__ h00, const float* __restrict__ c00,
    const float* __restrict__ h01, const float* __restrict__ c01,
    const float* __restrict__ Wih0, const float* __restrict__ Whh0,
    const float* __restrict__ bih0, const float* __restrict__ bhh0,
    const float* __restrict__ Wih1, const float* __restrict__ Whh1,
    const float* __restrict__ bih1, const float* __restrict__ bhh1,
    float* out)
{
    const int tid  = threadIdx.x;
    const int bid  = blockIdx.x;
    const int role = bid >> 6;            // 0: layer0, 1: layer1
    const int j0   = (bid & 63) * 8;
    const int grp  = (bid & 63) >> 3;     // 8 counters x 8 CTAs per layer

    float* Wsf = sm + OFF_W;
    float* Cs  = sm + OFF_C;
    float* Bs  = sm + OFF_B;

    float* yout = out;
    float* h1f  = out + (size_t)T_ * B_ * H_;
    float* c1f  = h1f + B_ * H_;
    float* h2f  = c1f + B_ * H_;
    float* c2f  = h2f + B_ * H_;

    const int KX = (role == 0) ? C_ : H_;
    const int K  = KX + H_;
    const float* Wx    = (role == 0) ? Wih0 : Wih1;
    const float* Wh    = (role == 0) ? Whh0 : Whh1;
    const float* bi    = (role == 0) ? bih0 : bih1;
    const float* bh    = (role == 0) ? bhh0 : bhh1;
    const float* cinit = (role == 0) ? c00 : c01;

    // ---- one-time setup: weights [32 rows][K] = [Wx | Wh], bias, cell ----
    for (int idx = tid; idx < 32 * K; idx += NTHR_) {
        const int n = idx / K, k = idx - n * K;
        const int gr = (n >> 3) * H_ + j0 + (n & 7);
        const float v = (k < KX) ? Wx[(size_t)gr * KX + k]
                                 : Wh[(size_t)gr * H_ + (k - KX)];
        Wsf[n * 1028 + k] = v;
    }
    if (tid < 32) {
        const int gr = (tid >> 3) * H_ + j0 + (tid & 7);
        Bs[tid] = bi[gr] + bh[gr];
    }
    {
        const int m = tid & 63, jb = tid >> 6;
        Cs[jb * 65 + m]       = cinit[(size_t)m * H_ + j0 + jb];
        Cs[(jb + 4) * 65 + m] = cinit[(size_t)m * H_ + j0 + jb + 4];
    }
    __syncthreads();

    if (role == 0) {
        // layer0: x chunks [0,4) free, then h chunks [4,12) after own barrier
        for (int t = 0; t < T_; t++) {
            const float* hprev = (t == 0) ? h00 : (g_y0 + (size_t)(t - 1) * B_ * H_);
            lstm_step(tid, j0,
                      x + (size_t)t * B_ * C_, C_, 0, 4, nullptr, 0,
                      hprev, H_, 4, 12, g_bars0, t * 8,
                      g_y0 + (size_t)t * B_ * H_, t == T_ - 1, h1f, c1f,
                      &g_bars0[grp * 32]);
        }
    } else {
        // layer1: h chunks [8,16) after own barrier, then x chunks [0,8)
        // (src g_y0[t]) after layer0's barrier reaches t+1.
        for (int t = 0; t < T_; t++) {
            const float* hprev = (t == 0) ? h01 : (yout + (size_t)(t - 1) * B_ * H_);
            lstm_step(tid, j0,
                      hprev, H_, 8, 16, g_bars1, t * 8,
                      g_y0 + (size_t)t * B_ * H_, H_, 0, 8, g_bars0, (t + 1) * 8,
                      yout + (size_t)t * B_ * H_, t == T_ - 1, h2f, c2f,
                      &g_bars1[grp * 32]);
        }
    }
}

extern "C" void kernel_launch(void* const* d_in, const int* in_sizes, int n_in,
                              void* d_out, int out_size) {
    (void)in_sizes; (void)n_in; (void)out_size;
    cudaFuncSetAttribute(lstm_kernel, cudaFuncAttributeMaxDynamicSharedMemorySize,
                         SMEM_BYTES);
    reset_kernel<<<1, 32>>>();
    lstm_kernel<<<GRID_, NTHR_, SMEM_BYTES>>>(
        (const float*)d_in[0],
        (const float*)d_in[1], (const float*)d_in[2],
        (const float*)d_in[3], (const float*)d_in[4],
        (const float*)d_in[5], (const float*)d_in[6],
        (const float*)d_in[7], (const float*)d_in[8],
        (const float*)d_in[9], (const float*)d_in[10],
        (const float*)d_in[11], (const float*)d_in[12],
        (float*)d_out);
}

// round 9
// speedup vs baseline: 1.7339x; 1.6346x over previous
#include <cuda_runtime.h>
#include <cuda_bf16.h>
#include <cstdint>
#include <cstddef>

// MultiLayerLSTM via legacy mma.sync (bf16, m16n8k16) with fp32 bf16-split.
// A' = [batch-hi(64); batch-lo(64)] (M=128), per CTA N=32 gate rows, two W
// passes (Whi, Wlo) accumulated in registers; warp owns matched hi/lo m-tiles
// so the final fold is in-register. 64+64 CTAs (layer0 | layer1), decoupled
// per-layer progress counters (R5-R7 proven scheme).

#define T_ 1024
#define B_ 64
#define C_ 256
#define H_ 512
#define NTHR_ 256
#define GRID_ 128

// ---- shared memory byte offsets ----
#define OFF_BS  0                  // 32 float biases
#define OFF_GR  128                // 64 x 33 float gate matrix
#define OFF_A   9216               // 2 x 16KB A' tiles (128 rows x 64k bf16, SW128)
#define OFF_WH  41984              // 16 x 4KB Whi chunk tiles (32 x 64k, SW128)
#define OFF_WL  107520             // 16 x 4KB Wlo chunk tiles
#define SMEM_BYTES 173056

typedef __nv_bfloat16 bf16;

static __device__ __align__(256) bf16 g_xhi[(size_t)T_ * B_ * C_];
static __device__ __align__(256) bf16 g_xlo[(size_t)T_ * B_ * C_];
static __device__ __align__(256) bf16 g_y0hi[(size_t)T_ * B_ * H_];
static __device__ __align__(256) bf16 g_y0lo[(size_t)T_ * B_ * H_];
static __device__ __align__(256) bf16 g_h1hi[(size_t)T_ * B_ * H_];
static __device__ __align__(256) bf16 g_h1lo[(size_t)T_ * B_ * H_];
static __device__ __align__(256) bf16 g_h00hi[B_ * H_], g_h00lo[B_ * H_];
static __device__ __align__(256) bf16 g_h01hi[B_ * H_], g_h01lo[B_ * H_];
static __device__ int g_bars0[8 * 32];
static __device__ int g_bars1[8 * 32];

// ---- prep: split x, h00, h01 into bf16 hi/lo; reset counters ----
__global__ void prep_kernel(const float* __restrict__ x,
                            const float* __restrict__ h00,
                            const float* __restrict__ h01) {
    const size_t stride = (size_t)gridDim.x * blockDim.x;
    const size_t i0 = (size_t)blockIdx.x * blockDim.x + threadIdx.x;
    const size_t nx = (size_t)T_ * B_ * C_;
    for (size_t p = i0; p < nx; p += stride) {
        float v = x[p];
        bf16 h = __float2bfloat16(v);
        g_xhi[p] = h;
        g_xlo[p] = __float2bfloat16(v - __bfloat162float(h));
    }
    for (size_t p = i0; p < (size_t)B_ * H_; p += stride) {
        float v = h00[p];
        bf16 h = __float2bfloat16(v);
        g_h00hi[p] = h;
        g_h00lo[p] = __float2bfloat16(v - __bfloat162float(h));
        v = h01[p];
        h = __float2bfloat16(v);
        g_h01hi[p] = h;
        g_h01lo[p] = __float2bfloat16(v - __bfloat162float(h));
    }
    if (blockIdx.x == 0 && threadIdx.x < 8) {
        g_bars0[threadIdx.x * 32] = 0;
        g_bars1[threadIdx.x * 32] = 0;
    }
}

__device__ __forceinline__ uint32_t smem_u32(const void* p) {
    uint32_t a;
    asm("{ .reg .u64 t; cvta.to.shared.u64 t, %1; cvt.u32.u64 %0, t; }"
        : "=r"(a) : "l"(p));
    return a;
}
__device__ __forceinline__ void ldsm4(uint32_t addr, uint32_t* r) {
    asm volatile("ldmatrix.sync.aligned.m8n8.x4.shared.b16 {%0,%1,%2,%3}, [%4];"
                 : "=r"(r[0]), "=r"(r[1]), "=r"(r[2]), "=r"(r[3]) : "r"(addr));
}
__device__ __forceinline__ void ldsm2(uint32_t addr, uint32_t* r) {
    asm volatile("ldmatrix.sync.aligned.m8n8.x2.shared.b16 {%0,%1}, [%2];"
                 : "=r"(r[0]), "=r"(r[1]) : "r"(addr));
}
__device__ __forceinline__ void mma16816(float* c, const uint32_t* a,
                                         const uint32_t* b) {
    asm volatile(
        "mma.sync.aligned.m16n8k16.row.col.f32.bf16.bf16.f32 "
        "{%0,%1,%2,%3}, {%4,%5,%6,%7}, {%8,%9}, {%0,%1,%2,%3};"
        : "+f"(c[0]), "+f"(c[1]), "+f"(c[2]), "+f"(c[3])
        : "r"(a[0]), "r"(a[1]), "r"(a[2]), "r"(a[3]), "r"(b[0]), "r"(b[1]));
}
__device__ __forceinline__ float sigf(float v) { return 1.0f / (1.0f + __expf(-v)); }

__device__ __forceinline__ void wait_bars(const int* bars, int tid, int target) {
    if (tid < 8) {
        volatile const int* p = bars + tid * 32;
        while (*p < target) { }
        __threadfence();
    }
    __syncthreads();
}

extern __shared__ char smem8[];

// stage one A' chunk: rows 0-63 hi, 64-127 lo; 64 k cols; SW128 swizzled
__device__ __forceinline__ void ldgA(const bf16* __restrict__ shi,
                                     const bf16* __restrict__ slo,
                                     int rs, int col0, int tid, uint4* v) {
    #pragma unroll
    for (int it = 0; it < 4; it++) {
        const int seg = it * NTHR_ + tid;
        const int row = seg >> 3, s8 = seg & 7;
        const bf16* src = (row < 64 ? shi + (size_t)row * rs
                                    : slo + (size_t)(row - 64) * rs) + col0 + s8 * 8;
        v[it] = *(const uint4*)src;
    }
}
__device__ __forceinline__ void stsA(char* abuf, int tid, const uint4* v) {
    #pragma unroll
    for (int it = 0; it < 4; it++) {
        const int seg = it * NTHR_ + tid;
        const int row = seg >> 3, s8 = seg & 7;
        const uint32_t bo = row * 128 + s8 * 16;
        const uint32_t sw = bo ^ ((bo >> 3) & 0x70);
        *(uint4*)(abuf + sw) = v[it];
    }
}

__global__ void __launch_bounds__(NTHR_, 1) lstm_kernel(
    const float* __restrict__ x,
    const float* __restrict__ h00, const float* __restrict__ c00,
    const float* __restrict__ h01, const float* __restrict__ c01,
    const float* __restrict__ Wih0, const float* __restrict__ Whh0,
    const float* __restrict__ bih0, const float* __restrict__ bhh0,
    const float* __restrict__ Wih1, const float* __restrict__ Whh1,
    const float* __restrict__ bih1, const float* __restrict__ bhh1,
    float* out)
{
    const int tid  = threadIdx.x;
    const int wid  = tid >> 5;
    const int lid  = tid & 31;
    const int bid  = blockIdx.x;
    const int role = bid >> 6;            // 0: layer0, 1: layer1
    const int j0   = (bid & 63) * 8;
    const int grp  = (bid & 63) >> 3;

    const uint32_t sb = smem_u32(smem8);
    float* Bs = (float*)(smem8 + OFF_BS);
    float* Gr = (float*)(smem8 + OFF_GR);   // [64][33]

    const int KX = role ? H_ : C_;
    const int K  = KX + H_;
    const float* Wx    = role ? Wih1 : Wih0;
    const float* Wh    = role ? Whh1 : Whh0;
    const float* bi    = role ? bih1 : bih0;
    const float* bh    = role ? bhh1 : bhh0;
    const float* cinit = role ? c01 : c00;

    // ---- one-time: split weights into SW128 chunk tiles (hi, lo) ----
    for (int idx = tid; idx < 32 * K; idx += NTHR_) {
        const int n = idx / K, k = idx - n * K;
        const int gr = (n >> 3) * H_ + j0 + (n & 7);
        const float v = (k < KX) ? Wx[(size_t)gr * KX + k]
                                 : Wh[(size_t)gr * H_ + (k - KX)];
        const bf16 hb = __float2bfloat16(v);
        const bf16 lb = __float2bfloat16(v - __bfloat162float(hb));
        const int wc = k >> 6, kk = k & 63;
        const uint32_t bo = n * 128 + kk * 2;
        const uint32_t sw = bo ^ ((bo >> 3) & 0x70);
        *(bf16*)(smem8 + OFF_WH + wc * 4096 + sw) = hb;
        *(bf16*)(smem8 + OFF_WL + wc * 4096 + sw) = lb;
    }
    if (tid < 32) {
        const int gr = (tid >> 3) * H_ + j0 + (tid & 7);
        Bs[tid] = bi[gr] + bh[gr];
    }
    float creg[8];
    if (tid < 64) {
        #pragma unroll
        for (int jj = 0; jj < 8; jj++)
            creg[jj] = cinit[(size_t)tid * H_ + j0 + jj];
    }
    __syncthreads();

    // warp decomposition: 4 m-slabs x 2 n-slabs
    const int mw = wid & 3;               // m-slab: hi rows 16mw, lo rows 64+16mw
    const int nw = wid >> 2;              // n-slab: cols 16nw
    // ldmatrix lane geometry (constant per thread)
    const int jA = lid >> 3, rA = lid & 7;
    const int rowA  = ((jA & 1) << 3) + rA;       // 0..15 within m-tile
    const int colA2 = (jA >> 1) << 4;             // byte col offset 0/16
    const uint32_t swA = (uint32_t)rA << 4;
    const int jB = (lid >> 3) & 1, rB = lid & 7;
    const int colB2 = jB << 4;
    const uint32_t swB = (uint32_t)rB << 4;
    // per-thread fixed parts of addresses
    const uint32_t aHiBase = (uint32_t)(16 * mw + rowA) * 128;
    const uint32_t aLoBase = (uint32_t)(64 + 16 * mw + rowA) * 128;
    const uint32_t bRow0   = (uint32_t)(16 * nw + rB) * 128;       // nt=0
    const uint32_t bRow1   = (uint32_t)(16 * nw + 8 + rB) * 128;   // nt=1

    float* yout = out;
    float* h1f  = out + (size_t)T_ * B_ * H_;
    float* c1f  = h1f + B_ * H_;
    float* h2f  = c1f + B_ * H_;
    float* c2f  = h2f + B_ * H_;
    float* hTd  = role ? h2f : h1f;
    float* cTd  = role ? c2f : c1f;
    int* actr   = (role ? g_bars1 : g_bars0) + grp * 32;

    for (int t = 0; t < T_; t++) {
        float acc[2][2][4];               // [hi/lo mtile][ntile][4]
        #pragma unroll
        for (int i = 0; i < 2; i++)
            #pragma unroll
            for (int j = 0; j < 2; j++)
                #pragma unroll
                for (int q = 0; q < 4; q++) acc[i][j][q] = 0.0f;

        int ab = 0;
        #pragma unroll 1
        for (int sg = 0; sg < 2; sg++) {
            // ---- resolve segment: src hi/lo, row stride, chunks, weights ----
            const bf16 *shi, *slo;
            int rs, nch, wc0;
            const int* bw; int tw;
            if (role == 0) {
                if (sg == 0) {            // x part, no wait
                    shi = g_xhi + (size_t)t * B_ * C_;
                    slo = g_xlo + (size_t)t * B_ * C_;
                    rs = C_; nch = 4; wc0 = 0; bw = nullptr; tw = 0;
                } else {                  // h part after own barrier
                    if (t == 0) { shi = g_h00hi; slo = g_h00lo; }
                    else {
                        shi = g_y0hi + (size_t)(t - 1) * B_ * H_;
                        slo = g_y0lo + (size_t)(t - 1) * B_ * H_;
                    }
                    rs = H_; nch = 8; wc0 = 4; bw = g_bars0; tw = t * 8;
                }
            } else {
                if (sg == 0) {            // h part after own barrier
                    if (t == 0) { shi = g_h01hi; slo = g_h01lo; }
                    else {
                        shi = g_h1hi + (size_t)(t - 1) * B_ * H_;
                        slo = g_h1lo + (size_t)(t - 1) * B_ * H_;
                    }
                    rs = H_; nch = 8; wc0 = 8; bw = g_bars1; tw = t * 8;
                } else {                  // y0 part after layer0 progress
                    shi = g_y0hi + (size_t)t * B_ * H_;
                    slo = g_y0lo + (size_t)t * B_ * H_;
                    rs = H_; nch = 8; wc0 = 0; bw = g_bars0; tw = (t + 1) * 8;
                }
            }
            if (bw) wait_bars(bw, tid, tw);

            {   // direct-stage first chunk of segment
                uint4 v[4];
                ldgA(shi, slo, rs, 0, tid, v);
                stsA(smem8 + OFF_A + ab * 16384, tid, v);
            }
            for (int c = 0; c < nch; c++) {
                __syncthreads();          // staged buffer visible; other free
                uint4 v[4];
                const bool pf = (c + 1 < nch);
                if (pf) ldgA(shi, slo, rs, (c + 1) * 64, tid, v);

                // ---- compute chunk: 4 k-steps ----
                const uint32_t aBase = sb + OFF_A + ab * 16384;
                const uint32_t wcb   = (uint32_t)(wc0 + c) * 4096;
                const uint32_t whB   = sb + OFF_WH + wcb;
                const uint32_t wlB   = sb + OFF_WL + wcb;
                #pragma unroll
                for (int ks = 0; ks < 4; ks++) {
                    const uint32_t kA = (uint32_t)((ks * 32 + colA2) ^ (int)swA);
                    const uint32_t kB = (uint32_t)((ks * 32 + colB2) ^ (int)swB);
                    uint32_t ah[4], al[4], bh0[2], bh1[2], bl0[2], bl1[2];
                    ldsm4(aBase + aHiBase + kA, ah);
                    ldsm4(aBase + aLoBase + kA, al);
                    ldsm2(whB + bRow0 + kB, bh0);
                    ldsm2(whB + bRow1 + kB, bh1);
                    ldsm2(wlB + bRow0 + kB, bl0);
                    ldsm2(wlB + bRow1 + kB, bl1);
                    mma16816(acc[0][0], ah, bh0);
                    mma16816(acc[0][1], ah, bh1);
                    mma16816(acc[1][0], al, bh0);
                    mma16816(acc[1][1], al, bh1);
                    mma16816(acc[0][0], ah, bl0);
                    mma16816(acc[0][1], ah, bl1);
                    mma16816(acc[1][0], al, bl0);
                    mma16816(acc[1][1], al, bl1);
                }
                if (pf) stsA(smem8 + OFF_A + (ab ^ 1) * 16384, tid, v);
                ab ^= 1;
            }
        }
        __syncthreads();

        // ---- fold hi+lo m-tiles, write gates to Gr[64][33] ----
        {
            const int mrow = 16 * mw + (lid >> 2);
            const int col0 = 16 * nw + 2 * (lid & 3);
            #pragma unroll
            for (int nt = 0; nt < 2; nt++) {
                const int cc = col0 + nt * 8;
                Gr[mrow * 33 + cc]           = acc[0][nt][0] + acc[1][nt][0];
                Gr[mrow * 33 + cc + 1]       = acc[0][nt][1] + acc[1][nt][1];
                Gr[(mrow + 8) * 33 + cc]     = acc[0][nt][2] + acc[1][nt][2];
                Gr[(mrow + 8) * 33 + cc + 1] = acc[0][nt][3] + acc[1][nt][3];
            }
        }
        __syncthreads();

        // ---- pointwise + h/c update (threads 0-63 = batch rows) ----
        if (tid < 64) {
            const int m = tid;
            float hv[8];
            #pragma unroll
            for (int jj = 0; jj < 8; jj++) {
                float gi = Gr[m * 33 + jj]      + Bs[jj];
                float gf = Gr[m * 33 + 8 + jj]  + Bs[8 + jj];
                float gg = Gr[m * 33 + 16 + jj] + Bs[16 + jj];
                float go = Gr[m * 33 + 24 + jj] + Bs[24 + jj];
                gi = sigf(gi); gf = sigf(gf); gg = tanhf(gg); go = sigf(go);
                const float cv = gf * creg[jj] + gi * gg;
                creg[jj] = cv;
                hv[jj] = go * tanhf(cv);
            }
            uint32_t phh[4], pll[4];
            #pragma unroll
            for (int q = 0; q < 4; q++) {
                const float a = hv[2 * q], b = hv[2 * q + 1];
                const bf16 ba = __float2bfloat16(a), bb = __float2bfloat16(b);
                phh[q] = (uint32_t)__bfloat16_as_ushort(ba) |
                         ((uint32_t)__bfloat16_as_ushort(bb) << 16);
                const bf16 la = __float2bfloat16(a - __bfloat162float(ba));
                const bf16 lb = __float2bfloat16(b - __bfloat162float(bb));
                pll[q] = (uint32_t)__bfloat16_as_ushort(la) |
                         ((uint32_t)__bfloat16_as_ushort(lb) << 16);
            }
            bf16* dsthi = (role ? g_h1hi : g_y0hi) + (size_t)t * B_ * H_
                          + (size_t)m * H_ + j0;
            bf16* dstlo = (role ? g_h1lo : g_y0lo) + (size_t)t * B_ * H_
                          + (size_t)m * H_ + j0;
            *(uint4*)dsthi = make_uint4(phh[0], phh[1], phh[2], phh[3]);
            *(uint4*)dstlo = make_uint4(pll[0], pll[1], pll[2], pll[3]);
            if (role) {
                float* od = yout + (size_t)t * B_ * H_ + (size_t)m * H_ + j0;
                *(float4*)od       = make_float4(hv[0], hv[1], hv[2], hv[3]);
                *(float4*)(od + 4) = make_float4(hv[4], hv[5], hv[6], hv[7]);
            }
            if (t == T_ - 1) {
                float* hd = hTd + (size_t)m * H_ + j0;
                *(float4*)hd       = make_float4(hv[0], hv[1], hv[2], hv[3]);
                *(float4*)(hd + 4) = make_float4(hv[4], hv[5], hv[6], hv[7]);
                float* cd = cTd + (size_t)m * H_ + j0;
                *(float4*)cd       = make_float4(creg[0], creg[1], creg[2], creg[3]);
                *(float4*)(cd + 4) = make_float4(creg[4], creg[5], creg[6], creg[7]);
            }
            __threadfence();
        }
        __syncthreads();
        if (tid == 0) atomicAdd(actr, 1);
    }
}

extern "C" void kernel_launch(void* const* d_in, const int* in_sizes, int n_in,
                              void* d_out, int out_size) {
    (void)in_sizes; (void)n_in; (void)out_size;
    cudaFuncSetAttribute(lstm_kernel, cudaFuncAttributeMaxDynamicSharedMemorySize,
                         SMEM_BYTES);
    prep_kernel<<<1024, 256>>>((const float*)d_in[0], (const float*)d_in[1],
                               (const float*)d_in[3]);
    lstm_kernel<<<GRID_, NTHR_, SMEM_BYTES>>>(
        (const float*)d_in[0],
        (const float*)d_in[1], (const float*)d_in[2],
        (const float*)d_in[3], (const float*)d_in[4],
        (const float*)d_in[5], (const float*)d_in[6],
        (const float*)d_in[7], (const float*)d_in[8],
        (const float*)d_in[9], (const float*)d_in[10],
        (const float*)d_in[11], (const float*)d_in[12],
        (float*)d_out);
}